// round 2
// baseline (speedup 1.0000x reference)
#include <cuda_runtime.h>
#include <cuda_bf16.h>

// StyleLoss: one-pass raw-moment reduction (k=1..5) per channel over axis (B,H,W),
// central moments via binomial identity, then loss = sum_k sqrt(sum_c (mx_k - my_k)^2).
//
// Shapes (hardcoded from reference): x, target: [8, 256, 128, 128] f32.
// Per channel N = 8*128*128 = 131072 elements, laid out as 8 contiguous
// segments of 16384 floats at stride 256*16384.

#define B_DIM 8
#define C_DIM 256
#define HW 16384              // 128*128, contiguous per (b, c)
#define HW4 4096              // HW / 4 (float4)
#define N_PER_C 131072        // B * HW
#define NSLICE 8              // one slice per batch index
#define NMOM 10               // 5 moments for x, 5 for y

// Scratch for per-(channel, slice) partial sums. 256*8*10 floats = 80 KB.
__device__ float g_part[C_DIM * NSLICE * NMOM];

// Accumulate x, x^2, x^3, x^4, x^5 into s1..s5 (7 fp ops per element).
__device__ __forceinline__ void acc_powers(float v, float& s1, float& s2,
                                           float& s3, float& s4, float& s5) {
    float v2 = v * v;
    s1 += v;
    s2 += v2;
    s3 = fmaf(v2, v, s3);
    float v4 = v2 * v2;
    s4 += v4;
    s5 = fmaf(v4, v, s5);
}

__device__ __forceinline__ float warp_sum(float v) {
    #pragma unroll
    for (int o = 16; o > 0; o >>= 1)
        v += __shfl_xor_sync(0xFFFFFFFFu, v, o);
    return v;
}

__global__ void __launch_bounds__(256)
moments_kernel(const float4* __restrict__ x, const float4* __restrict__ y) {
    const int s = blockIdx.x;   // batch slice 0..7
    const int c = blockIdx.y;   // channel 0..255
    const int tid = threadIdx.x;

    // float4 base of segment (b=s, c): ((s*C + c) * HW) / 4
    const long base = (long)(s * C_DIM + c) * HW4;

    float a1 = 0.f, a2 = 0.f, a3 = 0.f, a4 = 0.f, a5 = 0.f;  // x moments
    float b1 = 0.f, b2 = 0.f, b3 = 0.f, b4 = 0.f, b5 = 0.f;  // y moments

    #pragma unroll
    for (int i = 0; i < HW4 / 256; i++) {           // 16 iterations
        float4 va = x[base + tid + i * 256];
        float4 vb = y[base + tid + i * 256];
        acc_powers(va.x, a1, a2, a3, a4, a5);
        acc_powers(va.y, a1, a2, a3, a4, a5);
        acc_powers(va.z, a1, a2, a3, a4, a5);
        acc_powers(va.w, a1, a2, a3, a4, a5);
        acc_powers(vb.x, b1, b2, b3, b4, b5);
        acc_powers(vb.y, b1, b2, b3, b4, b5);
        acc_powers(vb.z, b1, b2, b3, b4, b5);
        acc_powers(vb.w, b1, b2, b3, b4, b5);
    }

    // Deterministic reduction: warp shuffles, then 8-warp combine in shared.
    float m[NMOM] = {a1, a2, a3, a4, a5, b1, b2, b3, b4, b5};
    #pragma unroll
    for (int k = 0; k < NMOM; k++) m[k] = warp_sum(m[k]);

    __shared__ float sm[8][NMOM];
    const int wid = tid >> 5;
    const int lid = tid & 31;
    if (lid == 0) {
        #pragma unroll
        for (int k = 0; k < NMOM; k++) sm[wid][k] = m[k];
    }
    __syncthreads();

    if (tid < NMOM) {
        float tot = 0.f;
        #pragma unroll
        for (int w = 0; w < 8; w++) tot += sm[w][tid];
        g_part[(c * NSLICE + s) * NMOM + tid] = tot;
    }
}

__global__ void __launch_bounds__(256)
finalize_kernel(float* __restrict__ out) {
    const int c = threadIdx.x;  // one thread per channel

    // Sum the 8 slice partials in double.
    double E[NMOM];
    #pragma unroll
    for (int k = 0; k < NMOM; k++) {
        double t = 0.0;
        #pragma unroll
        for (int s = 0; s < NSLICE; s++)
            t += (double)g_part[(c * NSLICE + s) * NMOM + k];
        E[k] = t;
    }

    const double invN = 1.0 / (double)N_PER_C;
    double d2[5];  // squared per-channel differences per order

    // x central moments
    double mx = E[0] * invN;
    double Ex2 = E[1] * invN, Ex3 = E[2] * invN, Ex4 = E[3] * invN, Ex5 = E[4] * invN;
    double mx2 = mx * mx, mx3 = mx2 * mx;
    double cx2 = Ex2 - mx2;
    double cx3 = Ex3 - 3.0 * mx * Ex2 + 2.0 * mx3;
    double cx4 = Ex4 - 4.0 * mx * Ex3 + 6.0 * mx2 * Ex2 - 3.0 * mx2 * mx2;
    double cx5 = Ex5 - 5.0 * mx * Ex4 + 10.0 * mx2 * Ex3 - 10.0 * mx3 * Ex2 + 4.0 * mx3 * mx2;

    // y central moments
    double my = E[5] * invN;
    double Ey2 = E[6] * invN, Ey3 = E[7] * invN, Ey4 = E[8] * invN, Ey5 = E[9] * invN;
    double my2 = my * my, my3 = my2 * my;
    double cy2 = Ey2 - my2;
    double cy3 = Ey3 - 3.0 * my * Ey2 + 2.0 * my3;
    double cy4 = Ey4 - 4.0 * my * Ey3 + 6.0 * my2 * Ey2 - 3.0 * my2 * my2;
    double cy5 = Ey5 - 5.0 * my * Ey4 + 10.0 * my2 * Ey3 - 10.0 * my3 * Ey2 + 4.0 * my3 * my2;

    double d;
    d = mx  - my;  d2[0] = d * d;
    d = cx2 - cy2; d2[1] = d * d;
    d = cx3 - cy3; d2[2] = d * d;
    d = cx4 - cy4; d2[3] = d * d;
    d = cx5 - cy5; d2[4] = d * d;

    // Reduce each order over 256 channels, then loss = sum of sqrts.
    __shared__ double red[256];
    __shared__ double acc;
    if (c == 0) acc = 0.0;

    for (int ord = 0; ord < 5; ord++) {
        __syncthreads();
        red[c] = d2[ord];
        __syncthreads();
        #pragma unroll
        for (int off = 128; off > 0; off >>= 1) {
            if (c < off) red[c] += red[c + off];
            __syncthreads();
        }
        if (c == 0) acc += sqrt(red[0]);   // weights are all 1.0
    }
    __syncthreads();
    if (c == 0) out[0] = (float)acc;
}

extern "C" void kernel_launch(void* const* d_in, const int* in_sizes, int n_in,
                              void* d_out, int out_size) {
    const float4* x = (const float4*)d_in[0];
    const float4* y = (const float4*)d_in[1];
    float* out = (float*)d_out;

    dim3 grid(NSLICE, C_DIM);
    moments_kernel<<<grid, 256>>>(x, y);
    finalize_kernel<<<1, 256>>>(out);
}

// round 6
// speedup vs baseline: 1.0639x; 1.0639x over previous
#include <cuda_runtime.h>
#include <cuda_bf16.h>

// StyleLoss fused one-pass: raw moments k=1..5 per channel (f32x2-packed math),
// last-arriving block performs the finalize (central moments + RMSE-sum) in-kernel.
//
// x, target: [8, 256, 128, 128] f32. Per channel N = 131072.

#define C_DIM 256
#define HW4 4096              // 128*128 / 4 floats (float4 per (b,c) segment)
#define N_PER_C 131072
#define NSLICE 8
#define NMOM 10
#define NBLOCKS (NSLICE * C_DIM)   // 2048

__device__ __align__(16) float g_part[C_DIM * NSLICE * NMOM];  // 80 KB
__device__ unsigned int g_count;   // zero-init; reset by last block each launch

// ---- packed f32x2 helpers ----
__device__ __forceinline__ unsigned long long pk2(float lo, float hi) {
    unsigned long long r;
    asm("mov.b64 %0, {%1, %2};" : "=l"(r) : "f"(lo), "f"(hi));
    return r;
}
__device__ __forceinline__ void upk2(unsigned long long p, float& lo, float& hi) {
    asm("mov.b64 {%0, %1}, %2;" : "=f"(lo), "=f"(hi) : "l"(p));
}
__device__ __forceinline__ unsigned long long mul2(unsigned long long a, unsigned long long b) {
    unsigned long long r;
    asm("mul.rn.f32x2 %0, %1, %2;" : "=l"(r) : "l"(a), "l"(b));
    return r;
}
__device__ __forceinline__ unsigned long long add2(unsigned long long a, unsigned long long b) {
    unsigned long long r;
    asm("add.rn.f32x2 %0, %1, %2;" : "=l"(r) : "l"(a), "l"(b));
    return r;
}
__device__ __forceinline__ unsigned long long fma2(unsigned long long a, unsigned long long b,
                                                   unsigned long long c) {
    unsigned long long r;
    asm("fma.rn.f32x2 %0, %1, %2, %3;" : "=l"(r) : "l"(a), "l"(b), "l"(c));
    return r;
}

// Accumulate packed pair p into s[0..4] = {v, v^2, v^3, v^4, v^5} sums (7 packed ops / 2 elems)
__device__ __forceinline__ void acc2(unsigned long long p, unsigned long long* s) {
    unsigned long long v2 = mul2(p, p);
    s[0] = add2(s[0], p);
    s[1] = add2(s[1], v2);
    s[2] = fma2(v2, p, s[2]);
    unsigned long long v4 = mul2(v2, v2);
    s[3] = add2(s[3], v4);
    s[4] = fma2(v4, p, s[4]);
}

__device__ __forceinline__ float warp_sum(float v) {
    #pragma unroll
    for (int o = 16; o > 0; o >>= 1)
        v += __shfl_xor_sync(0xFFFFFFFFu, v, o);
    return v;
}

__global__ void __launch_bounds__(256, 4)
style_loss_kernel(const float4* __restrict__ x, const float4* __restrict__ y,
                  float* __restrict__ out) {
    const int s   = blockIdx.x;   // batch slice 0..7
    const int c   = blockIdx.y;   // channel 0..255
    const int tid = threadIdx.x;

    const long base = (long)(s * C_DIM + c) * HW4;

    unsigned long long sx[5] = {0ull, 0ull, 0ull, 0ull, 0ull};
    unsigned long long sy[5] = {0ull, 0ull, 0ull, 0ull, 0ull};

    #pragma unroll
    for (int i = 0; i < HW4 / 256; i++) {            // 16 iters
        float4 va = x[base + tid + i * 256];
        float4 vb = y[base + tid + i * 256];
        acc2(pk2(va.x, va.y), sx);
        acc2(pk2(va.z, va.w), sx);
        acc2(pk2(vb.x, vb.y), sy);
        acc2(pk2(vb.z, vb.w), sy);
    }

    // Collapse packed lanes, then deterministic warp + block reduction.
    float m[NMOM];
    #pragma unroll
    for (int k = 0; k < 5; k++) {
        float lo, hi;
        upk2(sx[k], lo, hi); m[k]     = lo + hi;
        upk2(sy[k], lo, hi); m[5 + k] = lo + hi;
    }
    #pragma unroll
    for (int k = 0; k < NMOM; k++) m[k] = warp_sum(m[k]);

    __shared__ float sm[8][NMOM];
    const int wid = tid >> 5;
    const int lid = tid & 31;
    if (lid == 0) {
        #pragma unroll
        for (int k = 0; k < NMOM; k++) sm[wid][k] = m[k];
    }
    __syncthreads();

    if (tid < NMOM) {
        float tot = 0.f;
        #pragma unroll
        for (int w = 0; w < 8; w++) tot += sm[w][tid];
        g_part[(c * NSLICE + s) * NMOM + tid] = tot;
    }

    // ---- last-block finalize (threadfence-reduction pattern) ----
    __threadfence();
    __shared__ bool is_last;
    if (tid == 0)
        is_last = (atomicAdd(&g_count, 1u) == (unsigned)(NBLOCKS - 1));
    __syncthreads();
    if (!is_last) return;
    __threadfence();

    // One thread per channel. Per-channel partials are 80 contiguous floats
    // = 20 float4 loads (independent -> MLP 20, L2-hot).
    const float4* gp4 = (const float4*)g_part;
    double E[NMOM];
    #pragma unroll
    for (int k = 0; k < NMOM; k++) E[k] = 0.0;
    #pragma unroll
    for (int j = 0; j < 20; j++) {
        float4 v = gp4[tid * 20 + j];
        E[(4 * j + 0) % NMOM] += (double)v.x;
        E[(4 * j + 1) % NMOM] += (double)v.y;
        E[(4 * j + 2) % NMOM] += (double)v.z;
        E[(4 * j + 3) % NMOM] += (double)v.w;
    }

    const double invN = 1.0 / (double)N_PER_C;
    double mx  = E[0] * invN;
    double Ex2 = E[1] * invN, Ex3 = E[2] * invN, Ex4 = E[3] * invN, Ex5 = E[4] * invN;
    double mx2 = mx * mx, mx3 = mx2 * mx;
    double cx2 = Ex2 - mx2;
    double cx3 = Ex3 - 3.0 * mx * Ex2 + 2.0 * mx3;
    double cx4 = Ex4 - 4.0 * mx * Ex3 + 6.0 * mx2 * Ex2 - 3.0 * mx2 * mx2;
    double cx5 = Ex5 - 5.0 * mx * Ex4 + 10.0 * mx2 * Ex3 - 10.0 * mx3 * Ex2 + 4.0 * mx3 * mx2;

    double my  = E[5] * invN;
    double Ey2 = E[6] * invN, Ey3 = E[7] * invN, Ey4 = E[8] * invN, Ey5 = E[9] * invN;
    double my2 = my * my, my3 = my2 * my;
    double cy2 = Ey2 - my2;
    double cy3 = Ey3 - 3.0 * my * Ey2 + 2.0 * my3;
    double cy4 = Ey4 - 4.0 * my * Ey3 + 6.0 * my2 * Ey2 - 3.0 * my2 * my2;
    double cy5 = Ey5 - 5.0 * my * Ey4 + 10.0 * my2 * Ey3 - 10.0 * my3 * Ey2 + 4.0 * my3 * my2;

    double d2[5];
    double d;
    d = mx  - my;  d2[0] = d * d;
    d = cx2 - cy2; d2[1] = d * d;
    d = cx3 - cy3; d2[2] = d * d;
    d = cx4 - cy4; d2[3] = d * d;
    d = cx5 - cy5; d2[4] = d * d;

    __shared__ double red[256];
    __shared__ double acc;
    if (tid == 0) acc = 0.0;

    #pragma unroll
    for (int ord = 0; ord < 5; ord++) {
        __syncthreads();
        red[tid] = d2[ord];
        __syncthreads();
        #pragma unroll
        for (int off = 128; off > 0; off >>= 1) {
            if (tid < off) red[tid] += red[tid + off];
            __syncthreads();
        }
        if (tid == 0) acc += sqrt(red[0]);   // all weights 1.0
    }
    __syncthreads();
    if (tid == 0) {
        out[0] = (float)acc;
        g_count = 0;          // reset for next launch (stream-ordered)
    }
}

extern "C" void kernel_launch(void* const* d_in, const int* in_sizes, int n_in,
                              void* d_out, int out_size) {
    const float4* x = (const float4*)d_in[0];
    const float4* y = (const float4*)d_in[1];
    float* out = (float*)d_out;

    dim3 grid(NSLICE, C_DIM);
    style_loss_kernel<<<grid, 256>>>(x, y, out);
}